// round 16
// baseline (speedup 1.0000x reference)
#include <cuda_runtime.h>
#include <cuda_bf16.h>
#include <cstdint>

#define NN   10000
#define BB   32
#define DIN  2
#define HH   64
#define GIN  66
#define CC   (GIN*BB)        // 2112
#define MHOP 3
#define KF   (GIN*MHOP)      // 198

#define BM     128
#define BN     128
#define BK     64
#define KTILES 157                 // ceil(10000/64)
#define ASTRIDE 72                 // 64 + 8 pad (bf16 elems)
#define BSTRIDE 136                // 128 + 8 pad
#define ABYTES (BM*ASTRIDE*2)      // 18432
#define STG    (ABYTES + BK*BSTRIDE*2)   // 35840
#define GSMEM  (3*STG)                   // 107520  (2 CTAs/SM)

#define FP     204                 // feature smem pitch (floats): 204%32=12 -> conflict-free a-frags
#define WP     136                 // W smem pitch (floats): 136%32=8 -> conflict-free b-frags
#define FSM_FLOATS (64*FP + 2*8*WP)      // 13056 + 2176 = 15232
#define FSMEM  (FSM_FLOATS*4)            // 60928 B -> 3 CTAs/SM

// ------------------------- scratch (device globals; no allocation) -------------------------
__device__ __nv_bfloat16 g_Abf[(size_t)NN*NN];   // bf16 A [m][k]
__device__ __nv_bfloat16 g_Xbf[(size_t)NN*CC];   // hop-0 operand bf16 [node][c], c=d*32+b
__device__ __nv_bfloat16 g_Pbf[(size_t)NN*CC];   // hop-1 operand bf16
__device__ float g_Xf [(size_t)NN*CC];           // hop-0 fp32
__device__ float g_P1f[(size_t)NN*CC];           // hop-1 fp32
__device__ float g_P2f[(size_t)NN*CC];           // hop-2 fp32
__device__ float g_rs [(size_t)BB*NN*HH];        // r * states
__device__ float g_u  [(size_t)BB*NN*HH];        // u gate

// ------------------------- A fp32 -> bf16 -------------------------
__global__ void k_convertA(const float* __restrict__ A) {
    size_t i = ((size_t)blockIdx.x*blockDim.x + threadIdx.x)*4;
    if (i >= (size_t)NN*NN) return;
    float4 v = *(const float4*)(A + i);
    ((__nv_bfloat162*)(g_Abf + i))[0] = __float22bfloat162_rn(make_float2(v.x, v.y));
    ((__nv_bfloat162*)(g_Abf + i))[1] = __float22bfloat162_rn(make_float2(v.z, v.w));
}

// ------------------------- build X = concat(inputs, s or r*s), c = d*32+b -----------------
__global__ void k_buildX(const float* __restrict__ inputs, const float* __restrict__ st, int useRS) {
    int idx = blockIdx.x*blockDim.x + threadIdx.x;
    if (idx >= NN*CC) return;
    int n = idx / CC, c = idx % CC;
    int d = c >> 5, b = c & 31;
    float v;
    if (d < DIN)       v = inputs[((size_t)b*NN + n)*DIN + d];
    else if (useRS)    v = g_rs  [((size_t)b*NN + n)*HH  + (d-DIN)];
    else               v = st    [((size_t)b*NN + n)*HH  + (d-DIN)];
    g_Xf [idx] = v;
    g_Xbf[idx] = __float2bfloat16(v);
}

// ---- big GEMM: bf16 HMMA, CTA 128x128xBK64, warp tile 32x64, 3-stage, 2 CTAs/SM ----------
// mode 0: B = g_Xbf -> g_P1f (fp32) + g_Pbf (bf16);  mode 1: B = g_Pbf -> g_P2f = 2*acc - g_Xf
__global__ __launch_bounds__(256, 2) void k_gemm(int mode)
{
    extern __shared__ char sm[];
    const int tid = threadIdx.x, lane = tid & 31, wid = tid >> 5;
    const int wm = wid >> 1, wn = wid & 1;              // 4x2 warps, 32x64 warp tile
    const int m0 = blockIdx.y*BM, c0 = blockIdx.x*BN;
    const __nv_bfloat16* __restrict__ Bq = mode ? g_Pbf : g_Xbf;
    const uint32_t sb = (uint32_t)__cvta_generic_to_shared(sm);

    float acc[2][8][4];
    #pragma unroll
    for (int i = 0; i < 2; i++)
        #pragma unroll
        for (int j = 0; j < 8; j++)
            #pragma unroll
            for (int q = 0; q < 4; q++) acc[i][j][q] = 0.f;

    auto load = [&](int kt) {
        const int k0 = kt*BK;
        const uint32_t base = sb + (kt % 3)*STG;
        #pragma unroll
        for (int qq = 0; qq < 8; qq++) {
            int i = tid + qq*256;
            const __nv_bfloat16* gp; uint32_t dst; bool ok;
            if (i < 1024) {                               // A: 128 rows x 8 16B chunks
                int r = i >> 3, ch = i & 7;
                gp  = g_Abf + (size_t)(m0 + r)*NN + k0 + ch*8;
                ok  = (m0 + r < NN) && (k0 + ch*8 < NN);
                dst = base + (uint32_t)(r*ASTRIDE + ch*8)*2;
            } else {                                      // B: 64 k-rows x 16 chunks
                int j = i - 1024, r = j >> 4, ch = j & 15;
                gp  = Bq + (size_t)(k0 + r)*CC + c0 + ch*8;
                ok  = (k0 + r < NN) && (c0 + ch*8 < CC);
                dst = base + (uint32_t)ABYTES + (uint32_t)(r*BSTRIDE + ch*8)*2;
            }
            int bytes = ok ? 16 : 0;
            if (!ok) gp = g_Abf;
            asm volatile("cp.async.cg.shared.global [%0],[%1],16,%2;"
                         :: "r"(dst), "l"(gp), "r"(bytes));
        }
        asm volatile("cp.async.commit_group;" ::: "memory");
    };

    load(0); load(1);

    for (int kt = 0; kt < KTILES; kt++) {
        asm volatile("cp.async.wait_group 1;" ::: "memory");
        __syncthreads();
        if (kt + 2 < KTILES) load(kt + 2);
        else asm volatile("cp.async.commit_group;" ::: "memory");

        const uint32_t aS = sb + (kt % 3)*STG;
        const uint32_t bS = aS + ABYTES;
        #pragma unroll
        for (int kk = 0; kk < 4; kk++) {
            uint32_t a[2][4];
            #pragma unroll
            for (int mt = 0; mt < 2; mt++) {
                uint32_t ad = aS + (uint32_t)((wm*32 + mt*16 + (lane & 15))*ASTRIDE
                                              + kk*16 + (lane >> 4)*8)*2;
                asm volatile("ldmatrix.sync.aligned.m8n8.x4.shared.b16 {%0,%1,%2,%3},[%4];"
                    : "=r"(a[mt][0]),"=r"(a[mt][1]),"=r"(a[mt][2]),"=r"(a[mt][3]) : "r"(ad));
            }
            uint32_t b[8][2];
            #pragma unroll
            for (int nj = 0; nj < 4; nj++) {
                uint32_t bd = bS + (uint32_t)((kk*16 + (lane & 15))*BSTRIDE
                                              + wn*64 + nj*16 + (lane >> 4)*8)*2;
                asm volatile("ldmatrix.sync.aligned.m8n8.x4.trans.shared.b16 {%0,%1,%2,%3},[%4];"
                    : "=r"(b[2*nj][0]),"=r"(b[2*nj][1]),"=r"(b[2*nj+1][0]),"=r"(b[2*nj+1][1]) : "r"(bd));
            }
            #pragma unroll
            for (int mt = 0; mt < 2; mt++)
                #pragma unroll
                for (int ni = 0; ni < 8; ni++)
                    asm volatile("mma.sync.aligned.m16n8k16.row.col.f32.bf16.bf16.f32 "
                        "{%0,%1,%2,%3},{%4,%5,%6,%7},{%8,%9},{%0,%1,%2,%3};"
                        : "+f"(acc[mt][ni][0]),"+f"(acc[mt][ni][1]),
                          "+f"(acc[mt][ni][2]),"+f"(acc[mt][ni][3])
                        : "r"(a[mt][0]),"r"(a[mt][1]),"r"(a[mt][2]),"r"(a[mt][3]),
                          "r"(b[ni][0]),"r"(b[ni][1]));
        }
    }

    float* __restrict__ outF = mode ? g_P2f : g_P1f;
    #pragma unroll
    for (int mt = 0; mt < 2; mt++)
        #pragma unroll
        for (int ni = 0; ni < 8; ni++) {
            int col = c0 + wn*64 + ni*8 + (lane & 3)*2;
            #pragma unroll
            for (int h = 0; h < 2; h++) {
                int row = m0 + wm*32 + mt*16 + (lane >> 2) + h*8;
                if (row < NN && col < CC) {
                    size_t o = (size_t)row*CC + col;
                    float v0 = acc[mt][ni][2*h], v1 = acc[mt][ni][2*h+1];
                    if (mode) {
                        v0 = 2.f*v0 - g_Xf[o];
                        v1 = 2.f*v1 - g_Xf[o+1];
                    }
                    outF[o] = v0; outF[o+1] = v1;
                    if (!mode)
                        *(__nv_bfloat162*)(g_Pbf + o) =
                            __float22bfloat162_rn(make_float2(v0, v1));
                }
            }
        }
}

// ---- feature tile loader: 64 rows (R0..R0+63) x K=198 (padded to 200) into fsm, tf32 -----
__device__ __forceinline__ void load_ftile(float* fsm, int R0, int tid) {
    for (int idx = tid; idx < 200*64; idx += 128) {
        int k = idx >> 6, lr = idx & 63;               // k-major: 32 consecutive rows coalesce
        float v = 0.f;
        if (k < KF) {
            int d = k/3, m = k%3;
            int R = R0 + lr, n = R >> 5, b = R & 31;
            const float* src = (m==0) ? g_Xf : (m==1) ? g_P1f : g_P2f;
            v = src[(size_t)n*CC + d*BB + b];
        }
        uint32_t t; asm("cvt.rna.tf32.f32 %0,%1;" : "=r"(t) : "f"(v));
        fsm[lr*FP + k] = __uint_as_float(t);
    }
}

// --------------- feature GEMM RU: (320000 x 198) @ (198 x 128), tf32 mma ------------------
__global__ __launch_bounds__(128) void k_featRU(
    const float* __restrict__ Wru, const float* __restrict__ bru,
    const float* __restrict__ states)
{
    extern __shared__ float fsm[];
    float* wsm = fsm + 64*FP;                       // [2][8][WP]
    const int tid = threadIdx.x, lane = tid & 31, wid = tid >> 5;
    const int R0 = blockIdx.x*64;

    load_ftile(fsm, R0, tid);
    auto stageW = [&](int s, int buf) {
        for (int i = tid; i < 1024; i += 128) {     // 8 k x 128 cols, coalesced
            int col = i & 127, kk = i >> 7, k = s*8 + kk;
            float v = (k < KF) ? Wru[k*128 + col] : 0.f;
            uint32_t t; asm("cvt.rna.tf32.f32 %0,%1;" : "=r"(t) : "f"(v));
            wsm[buf*(8*WP) + kk*WP + col] = __uint_as_float(t);
        }
    };
    stageW(0, 0);
    __syncthreads();

    float acc[16][4];
    #pragma unroll
    for (int j = 0; j < 16; j++)
        #pragma unroll
        for (int q = 0; q < 4; q++) acc[j][q] = 0.f;

    const int rA = wid*16 + (lane >> 2);
    for (int s = 0; s < 25; s++) {
        if (s + 1 < 25) stageW(s + 1, (s + 1) & 1);
        const int kb = s*8 + (lane & 3);
        uint32_t a0 = __float_as_uint(fsm[ rA     *FP + kb  ]);
        uint32_t a1 = __float_as_uint(fsm[(rA + 8)*FP + kb  ]);
        uint32_t a2 = __float_as_uint(fsm[ rA     *FP + kb+4]);
        uint32_t a3 = __float_as_uint(fsm[(rA + 8)*FP + kb+4]);
        const float* wb = wsm + (s & 1)*(8*WP);
        #pragma unroll
        for (int t8 = 0; t8 < 16; t8++) {
            int colb = t8*8 + (lane >> 2);
            uint32_t b0 = __float_as_uint(wb[(lane & 3)    *WP + colb]);
            uint32_t b1 = __float_as_uint(wb[((lane & 3)+4)*WP + colb]);
            asm volatile("mma.sync.aligned.m16n8k8.row.col.f32.tf32.tf32.f32 "
                "{%0,%1,%2,%3},{%4,%5,%6,%7},{%8,%9},{%0,%1,%2,%3};"
                : "+f"(acc[t8][0]),"+f"(acc[t8][1]),"+f"(acc[t8][2]),"+f"(acc[t8][3])
                : "r"(a0),"r"(a1),"r"(a2),"r"(a3),"r"(b0),"r"(b1));
        }
        __syncthreads();
    }

    #pragma unroll
    for (int t8 = 0; t8 < 16; t8++) {
        int col = t8*8 + (lane & 3)*2;
        #pragma unroll
        for (int h = 0; h < 2; h++) {
            int rl = wid*16 + (lane >> 2) + h*8;
            int R = R0 + rl, n = R >> 5, b = R & 31;
            #pragma unroll
            for (int e = 0; e < 2; e++) {
                int o = col + e;
                float z = acc[t8][2*h + e] + bru[o];
                float sg = 1.f/(1.f + __expf(-z));
                if (o < HH) {
                    size_t oi = ((size_t)b*NN + n)*HH + o;
                    g_rs[oi] = sg * states[oi];
                } else {
                    g_u[((size_t)b*NN + n)*HH + (o - HH)] = sg;
                }
            }
        }
    }
}

// --------------- feature GEMM C: (320000 x 198) @ (198 x 64), tf32 mma, final gate --------
__global__ __launch_bounds__(128) void k_featC(
    const float* __restrict__ Wc, const float* __restrict__ bc,
    const float* __restrict__ states, float* __restrict__ out)
{
    extern __shared__ float fsm[];
    float* wsm = fsm + 64*FP;
    const int tid = threadIdx.x, lane = tid & 31, wid = tid >> 5;
    const int R0 = blockIdx.x*64;

    load_ftile(fsm, R0, tid);
    auto stageW = [&](int s, int buf) {
        for (int i = tid; i < 512; i += 128) {      // 8 k x 64 cols
            int col = i & 63, kk = i >> 6, k = s*8 + kk;
            float v = (k < KF) ? Wc[k*64 + col] : 0.f;
            uint32_t t; asm("cvt.rna.tf32.f32 %0,%1;" : "=r"(t) : "f"(v));
            wsm[buf*(8*WP) + kk*WP + col] = __uint_as_float(t);
        }
    };
    stageW(0, 0);
    __syncthreads();

    float acc[8][4];
    #pragma unroll
    for (int j = 0; j < 8; j++)
        #pragma unroll
        for (int q = 0; q < 4; q++) acc[j][q] = 0.f;

    const int rA = wid*16 + (lane >> 2);
    for (int s = 0; s < 25; s++) {
        if (s + 1 < 25) stageW(s + 1, (s + 1) & 1);
        const int kb = s*8 + (lane & 3);
        uint32_t a0 = __float_as_uint(fsm[ rA     *FP + kb  ]);
        uint32_t a1 = __float_as_uint(fsm[(rA + 8)*FP + kb  ]);
        uint32_t a2 = __float_as_uint(fsm[ rA     *FP + kb+4]);
        uint32_t a3 = __float_as_uint(fsm[(rA + 8)*FP + kb+4]);
        const float* wb = wsm + (s & 1)*(8*WP);
        #pragma unroll
        for (int t8 = 0; t8 < 8; t8++) {
            int colb = t8*8 + (lane >> 2);
            uint32_t b0 = __float_as_uint(wb[(lane & 3)    *WP + colb]);
            uint32_t b1 = __float_as_uint(wb[((lane & 3)+4)*WP + colb]);
            asm volatile("mma.sync.aligned.m16n8k8.row.col.f32.tf32.tf32.f32 "
                "{%0,%1,%2,%3},{%4,%5,%6,%7},{%8,%9},{%0,%1,%2,%3};"
                : "+f"(acc[t8][0]),"+f"(acc[t8][1]),"+f"(acc[t8][2]),"+f"(acc[t8][3])
                : "r"(a0),"r"(a1),"r"(a2),"r"(a3),"r"(b0),"r"(b1));
        }
        __syncthreads();
    }

    #pragma unroll
    for (int t8 = 0; t8 < 8; t8++) {
        int col = t8*8 + (lane & 3)*2;
        #pragma unroll
        for (int h = 0; h < 2; h++) {
            int rl = wid*16 + (lane >> 2) + h*8;
            int R = R0 + rl, n = R >> 5, b = R & 31;
            #pragma unroll
            for (int e = 0; e < 2; e++) {
                int o = col + e;
                float cz = tanhf(acc[t8][2*h + e] + bc[o]);
                size_t oi = ((size_t)b*NN + n)*HH + o;
                float u = g_u[oi];
                out[oi] = u*states[oi] + (1.f - u)*cz;
            }
        }
    }
}

// ------------------------- launch -------------------------
extern "C" void kernel_launch(void* const* d_in, const int* in_sizes, int n_in,
                              void* d_out, int out_size) {
    const float* inputs = (const float*)d_in[0];
    const float* states = (const float*)d_in[1];
    const float* A      = (const float*)d_in[2];
    const float* W_ru   = (const float*)d_in[3];
    const float* b_ru   = (const float*)d_in[4];
    const float* W_c    = (const float*)d_in[5];
    const float* b_c    = (const float*)d_in[6];
    float* out = (float*)d_out;

    static int inited = 0;
    if (!inited) {
        cudaFuncSetAttribute(k_gemm,   cudaFuncAttributeMaxDynamicSharedMemorySize, GSMEM);
        cudaFuncSetAttribute(k_featRU, cudaFuncAttributeMaxDynamicSharedMemorySize, FSMEM);
        cudaFuncSetAttribute(k_featC,  cudaFuncAttributeMaxDynamicSharedMemorySize, FSMEM);
        inited = 1;
    }

    dim3 gemmGrid((CC + BN - 1)/BN, (NN + BM - 1)/BM);   // 17 x 79
    const int featGrid = (NN*BB)/64;                     // 5000

    k_convertA<<<(int)(((size_t)NN*NN/4 + 255)/256), 256>>>(A);

    // gconv 1: x = [inputs, states]
    k_buildX<<<(NN*CC + 255)/256, 256>>>(inputs, states, 0);
    k_gemm<<<gemmGrid, 256, GSMEM>>>(0);             // P1 = A @ X
    k_gemm<<<gemmGrid, 256, GSMEM>>>(1);             // P2 = 2 A @ P1 - X
    k_featRU<<<featGrid, 128, FSMEM>>>(W_ru, b_ru, states);

    // gconv 2: x = [inputs, r*states]
    k_buildX<<<(NN*CC + 255)/256, 256>>>(inputs, states, 1);
    k_gemm<<<gemmGrid, 256, GSMEM>>>(0);             // Q1
    k_gemm<<<gemmGrid, 256, GSMEM>>>(1);             // Q2
    k_featC<<<featGrid, 128, FSMEM>>>(W_c, b_c, states, out);
}